// round 1
// baseline (speedup 1.0000x reference)
#include <cuda_runtime.h>
#include <cstdint>

#define B_ 4
#define L_ 512
#define D_ 256
#define U_ 64
#define TI 8
#define TJ 32
#define NTROW (L_/TI)   // 64 row tiles per batch

// scratch for projections (allowed: __device__ globals, no allocation)
__device__ float g_q[B_*L_*U_];
__device__ float g_k[B_*L_*U_];

__device__ __forceinline__ float tanh_ap(float x){ float y; asm("tanh.approx.f32 %0, %1;" : "=f"(y) : "f"(x)); return y; }
__device__ __forceinline__ float ex2_ap(float x){ float y; asm("ex2.approx.f32 %0, %1;" : "=f"(y) : "f"(x)); return y; }
__device__ __forceinline__ unsigned long long dup2(float x){
    unsigned long long r; asm("mov.b64 %0, {%1, %1};" : "=l"(r) : "f"(x)); return r;
}
__device__ __forceinline__ void fma2(unsigned long long &a, unsigned long long x, unsigned long long y){
    asm("fma.rn.f32x2 %0, %1, %2, %0;" : "+l"(a) : "l"(x), "l"(y));
}
__device__ __forceinline__ void mul2(unsigned long long &a, unsigned long long x){
    asm("mul.rn.f32x2 %0, %0, %1;" : "+l"(a) : "l"(x));
}
__device__ __forceinline__ float2 unpack2(unsigned long long v){
    float lo, hi; asm("mov.b64 {%0, %1}, %2;" : "=f"(lo), "=f"(hi) : "l"(v)); return make_float2(lo, hi);
}

// ---------------------------------------------------------------------------
// Phase 1: q = X@Wt ; k = X@Wx + bh   (packed f32x2 over u-pairs)
// 512 blocks x 128 threads. Blocks [0,256): q, [256,512): k.
// Each block: 8 rows. W staged in smem in two 128-row halves (stays < 48KB static).
// ---------------------------------------------------------------------------
__global__ void __launch_bounds__(128) proj_kernel(
    const float* __restrict__ X, const float* __restrict__ Wt,
    const float* __restrict__ Wx, const float* __restrict__ bh)
{
    __shared__ __align__(16) float W_s[128*U_];   // 32KB (half of W)
    __shared__ __align__(16) float x_s[8*D_];     // 8KB

    const int bid = blockIdx.x;
    const bool is_k = bid >= (B_*L_/8);
    const int rb = is_k ? bid - (B_*L_/8) : bid;
    const float* __restrict__ W = is_k ? Wx : Wt;
    const int t = threadIdx.x;
    const int row0 = rb * 8;

    for (int i = t; i < 8*D_; i += 128) x_s[i] = X[row0*D_ + i];

    const int quad = t & 15;        // u = quad*4
    const int r    = t >> 4;        // row 0..7
    const float* xr = x_s + r*D_;

    unsigned long long a01 = 0ull, a23 = 0ull;

    #pragma unroll
    for (int half = 0; half < 2; ++half) {
        __syncthreads();
        for (int i = t; i < 128*U_; i += 128) W_s[i] = W[half*128*U_ + i];
        __syncthreads();
        const float* xh = xr + half*128;
        #pragma unroll 4
        for (int d = 0; d < 128; ++d) {
            unsigned long long xx = dup2(xh[d]);
            ulonglong2 w2 = *reinterpret_cast<const ulonglong2*>(W_s + d*U_ + quad*4);
            fma2(a01, xx, w2.x);
            fma2(a23, xx, w2.y);
        }
    }

    float2 v01 = unpack2(a01), v23 = unpack2(a23);
    if (is_k) {
        v01.x += bh[quad*4+0]; v01.y += bh[quad*4+1];
        v23.x += bh[quad*4+2]; v23.y += bh[quad*4+3];
    }
    float4 o; o.x = v01.x; o.y = v01.y; o.z = v23.x; o.w = v23.y;
    float* dst = (is_k ? g_k : g_q) + (row0 + r)*U_ + quad*4;
    *reinterpret_cast<float4*>(dst) = o;
}

// ---------------------------------------------------------------------------
// Phase 2: flash-style causal additive attention.
// 128 CTAs x 256 threads. CTA bid: b = bid>>5, pr = bid&31;
// processes row-tiles {pr, 63-pr} (triangular load balance).
// Score: warp w = row i0+w, lane = j. exp domain = log2 (Wa pre-scaled).
// PV: thread t -> d-pair (t&127), row-half (t>>7); packed fma.rn.f32x2.
// ---------------------------------------------------------------------------
__global__ void __launch_bounds__(256) attn_kernel(
    const float* __restrict__ X, const float* __restrict__ Wa,
    float* __restrict__ out)
{
    __shared__ __align__(16) float4 k_q[16*TJ];     // [uq][j]   8KB
    __shared__ __align__(16) float  Xs[TJ*D_];      // [j][d]    32KB
    __shared__ __align__(16) float4 q_q[16*TI];     // [uq][i]   2KB
    __shared__ __align__(16) float4 wa4[16];        // 256B (pre-scaled by log2e)
    __shared__ __align__(16) float2 p2[TI][TJ];     // dup pairs 2KB
    __shared__ __align__(16) float2 alpha2[TI];
    __shared__ float sinv[TI];

    const int t = threadIdx.x;
    const int w = t >> 5, lane = t & 31;
    const int b  = blockIdx.x >> 5;
    const int pr = blockIdx.x & 31;

    const float* __restrict__ Xb = X   + b*L_*D_;
    const float* __restrict__ kb = g_k + b*L_*U_;
    const float* __restrict__ qb = g_q + b*L_*U_;

    if (t < U_) reinterpret_cast<float*>(wa4)[t] = Wa[t] * 1.4426950408889634f;

    const int dp  = t & 127;   // d pair index (d = 2dp, 2dp+1)
    const int ih  = t >> 7;    // row half: rows ih*4 .. ih*4+3
    const int ib0 = ih * 4;

    for (int pass = 0; pass < 2; ++pass) {
        const int it = pass ? (NTROW - 1 - pr) : pr;
        const int i0 = it * TI;
        const int ntj = (i0 + TI - 1)/TJ + 1;

        __syncthreads();   // guard q_q/smem reuse across passes (also wa4 on first)
        if (t < 16*TI) {
            int i = t >> 4, uq = t & 15;
            q_q[uq*TI + i] = *reinterpret_cast<const float4*>(qb + (i0+i)*U_ + uq*4);
        }

        float m_run = -1e30f, s_run = 0.f;
        unsigned long long acc[4] = {0ull, 0ull, 0ull, 0ull};
        const int gi = i0 + w;

        for (int jt = 0; jt < ntj; ++jt) {
            const int j0 = jt * TJ;
            __syncthreads();   // prev v-update done (and q_q load on first iter)

            // ---- load k tile [uq][j] and X tile [j][d] ----
            #pragma unroll
            for (int rep = 0; rep < 2; ++rep) {
                int idx = t + rep*256;
                int uq = idx & 15, j = idx >> 4;
                k_q[uq*TJ + j] = *reinterpret_cast<const float4*>(kb + (j0+j)*U_ + uq*4);
            }
            #pragma unroll
            for (int rr = 0; rr < TJ; ++rr)
                Xs[rr*D_ + t] = Xb[(j0+rr)*D_ + t];
            __syncthreads();

            // ---- score: e[gi][j0+lane] in log2 domain ----
            float e0 = 0.f, e1 = 0.f;
            #pragma unroll
            for (int uq = 0; uq < 16; ++uq) {
                float4 kv = k_q[uq*TJ + lane];   // conflict-free
                float4 qv = q_q[uq*TI + w];      // broadcast
                float4 wa = wa4[uq];             // broadcast
                e0 += wa.x * tanh_ap(qv.x + kv.x);
                e1 += wa.y * tanh_ap(qv.y + kv.y);
                e0 += wa.z * tanh_ap(qv.z + kv.z);
                e1 += wa.w * tanh_ap(qv.w + kv.w);
            }
            float e = e0 + e1;
            const int gj = j0 + lane;
            if (gj > gi) e = -1e30f;   // causal: exp2 underflows to exact 0 (== ref's -10000 path)

            // ---- online softmax (warp = one row) ----
            float mt = e;
            #pragma unroll
            for (int off = 16; off; off >>= 1)
                mt = fmaxf(mt, __shfl_xor_sync(0xffffffffu, mt, off));
            float m_new = fmaxf(m_run, mt);
            float p = ex2_ap(e - m_new);
            float st = p;
            #pragma unroll
            for (int off = 16; off; off >>= 1)
                st += __shfl_xor_sync(0xffffffffu, st, off);
            float alpha = ex2_ap(m_run - m_new);
            s_run = s_run * alpha + st;
            m_run = m_new;
            p2[w][lane] = make_float2(p, p);            // pre-duplicated for f32x2
            if (lane == 0) alpha2[w] = make_float2(alpha, alpha);
            __syncthreads();

            // ---- PV update (packed f32x2 over d-pairs) ----
            #pragma unroll
            for (int i = 0; i < 4; ++i)
                mul2(acc[i], *reinterpret_cast<unsigned long long*>(&alpha2[ib0+i]));
            const unsigned long long* xcol =
                reinterpret_cast<const unsigned long long*>(Xs) + dp;   // stride 128/row
            #pragma unroll
            for (int j = 0; j < TJ; ++j) {
                unsigned long long xv = xcol[j*(D_/2)];
                #pragma unroll
                for (int i = 0; i < 4; ++i)
                    fma2(acc[i], xv, *reinterpret_cast<const unsigned long long*>(&p2[ib0+i][j]));
            }
        }

        // ---- finalize ----
        if (lane == 0) sinv[w] = 1.0f / s_run;
        __syncthreads();
        #pragma unroll
        for (int i = 0; i < 4; ++i) {
            float2 v = unpack2(acc[i]);
            float is = sinv[ib0 + i];
            float2 o = make_float2(v.x * is, v.y * is);
            *reinterpret_cast<float2*>(out + (b*L_ + i0 + ib0 + i)*D_ + dp*2) = o;
        }
    }
}

// ---------------------------------------------------------------------------
extern "C" void kernel_launch(void* const* d_in, const int* in_sizes, int n_in,
                              void* d_out, int out_size)
{
    const float* X  = (const float*)d_in[0];
    const float* Wt = (const float*)d_in[1];
    const float* Wx = (const float*)d_in[2];
    const float* bh = (const float*)d_in[3];
    const float* Wa = (const float*)d_in[4];
    // d_in[5] = ba : constant shift inside softmax -> mathematically a no-op

    proj_kernel<<<2*(B_*L_/8), 128>>>(X, Wt, Wx, bh);
    attn_kernel<<<B_*(NTROW/2), 256>>>(X, Wa, (float*)d_out);
}